// round 7
// baseline (speedup 1.0000x reference)
#include <cuda_runtime.h>
#include <cstdint>

#define THREADS 256
#define M_TILE  128

// ---------------- SMEM layout (bytes), MMA buffers 1024-aligned ----------------
#define OFF_B1   0
#define OFF_B2   256
#define OFF_XHI  1024
#define OFF_XLO  (OFF_XHI + 16384)     // 17408
#define OFF_W1HI (OFF_XLO + 16384)     // 33792
#define OFF_W1LO (OFF_W1HI + 24576)    // 58368
#define OFF_W2HI (OFF_W1LO + 24576)    // 82944
#define OFF_W2LO (OFF_W2HI + 8192)     // 91136
#define SMEM_BYTES (OFF_W2LO + 8192)   // 99328  -> 2 CTAs/SM

// ---------------- helpers ----------------
__device__ __forceinline__ uint32_t smem_u32(const void* p) {
    uint32_t a;
    asm("{ .reg .u64 t; cvta.to.shared.u64 t, %1; cvt.u32.u64 %0, t; }" : "=r"(a) : "l"(p));
    return a;
}
__device__ __forceinline__ uint32_t sw128(uint32_t o) { return o ^ ((o >> 3) & 0x70); }

__device__ __forceinline__ uint32_t pack2bf(float e0, float e1) {
    uint32_t r;
    asm("cvt.rn.bf16x2.f32 %0, %1, %2;" : "=r"(r) : "f"(e1), "f"(e0));
    return r;
}

// split 4 fp32 into bf16 hi/lo, 8B store each
__device__ __forceinline__ void split_store(char* hip, char* lop, float4 v) {
    uint32_t h01 = pack2bf(v.x, v.y);
    uint32_t h23 = pack2bf(v.z, v.w);
    float f0 = __uint_as_float(h01 << 16);
    float f1 = __uint_as_float(h01 & 0xFFFF0000u);
    float f2 = __uint_as_float(h23 << 16);
    float f3 = __uint_as_float(h23 & 0xFFFF0000u);
    uint32_t l01 = pack2bf(v.x - f0, v.y - f1);
    uint32_t l23 = pack2bf(v.z - f2, v.w - f3);
    *reinterpret_cast<uint2*>(hip) = make_uint2(h01, h23);
    *reinterpret_cast<uint2*>(lop) = make_uint2(l01, l23);
}

__device__ __forceinline__ void ldsm4(uint32_t r[4], uint32_t addr) {
    asm volatile("ldmatrix.sync.aligned.m8n8.x4.shared.b16 {%0,%1,%2,%3}, [%4];"
        : "=r"(r[0]), "=r"(r[1]), "=r"(r[2]), "=r"(r[3]) : "r"(addr));
}
__device__ __forceinline__ void ldsm4t(uint32_t r[4], uint32_t addr) {
    asm volatile("ldmatrix.sync.aligned.m8n8.x4.trans.shared.b16 {%0,%1,%2,%3}, [%4];"
        : "=r"(r[0]), "=r"(r[1]), "=r"(r[2]), "=r"(r[3]) : "r"(addr));
}
__device__ __forceinline__ void mma16816(float c[4], const uint32_t a[4], const uint32_t b[2]) {
    asm volatile(
        "mma.sync.aligned.m16n8k16.row.col.f32.bf16.bf16.f32 "
        "{%0,%1,%2,%3}, {%4,%5,%6,%7}, {%8,%9}, {%0,%1,%2,%3};"
        : "+f"(c[0]), "+f"(c[1]), "+f"(c[2]), "+f"(c[3])
        : "r"(a[0]), "r"(a[1]), "r"(a[2]), "r"(a[3]), "r"(b[0]), "r"(b[1]));
}
__device__ __forceinline__ uint32_t frag_addr(uint32_t base, int rbase, int cbase, int lane) {
    int row  = rbase + (lane & 15);
    int colb = cbase * 2 + (lane & 16);
    return base + sw128((uint32_t)(row * 128 + colb));
}
__device__ __forceinline__ void prefetch_l2(const void* p) {
    asm volatile("prefetch.global.L2 [%0];" :: "l"(p));
}
// pair barrier: 2 warps (64 threads) sharing one M band
__device__ __forceinline__ void pbar(int id) {
    asm volatile("bar.sync %0, 64;" :: "r"(id) : "memory");
}

__global__ __launch_bounds__(THREADS, 2)
void edge_mlp_mma(const float* __restrict__ src, const float* __restrict__ dst,
                  const float* __restrict__ ea,
                  const float* __restrict__ W1, const float* __restrict__ b1,
                  const float* __restrict__ W2, const float* __restrict__ b2,
                  float* __restrict__ out, int E, int ntiles)
{
    extern __shared__ char smem[];
    const uint32_t sb = smem_u32(smem);
    const int tid = threadIdx.x;
    const int lid = tid & 31;
    const int wid = tid >> 5;

    const int b  = wid >> 1;        // M band: rows 32b .. 32b+31 (pair of warps)
    const int wn = wid & 1;         // N group: cols 32*wn .. +31
    const int bar_id = b + 1;       // named barrier per pair (ids 1..4)

    // ================= ONE-TIME: biases + weights =================
    if (tid < 64) {
        ((float*)(smem + OFF_B1))[tid] = b1[tid];
        ((float*)(smem + OFF_B2))[tid] = b2[tid];
    }
    #pragma unroll
    for (int i = 0; i < 12; ++i) {
        int idx = tid + i * THREADS;               // float4 index, 0..3071
        uint32_t off = sw128((uint32_t)((idx >> 4) * 128 + (idx & 15) * 8));
        float4 v = ((const float4*)W1)[idx];
        split_store(smem + OFF_W1HI + off, smem + OFF_W1LO + off, v);
    }
    #pragma unroll
    for (int i = 0; i < 4; ++i) {
        int idx = tid + i * THREADS;               // 0..1023
        uint32_t off = sw128((uint32_t)((idx >> 4) * 128 + (idx & 15) * 8));
        float4 v = ((const float4*)W2)[idx];
        split_store(smem + OFF_W2HI + off, smem + OFF_W2LO + off, v);
    }
    __syncthreads();                               // the ONLY full-CTA barrier

    float acc[2][4][4];
    #pragma unroll
    for (int mt = 0; mt < 2; ++mt)
        #pragma unroll
        for (int nt = 0; nt < 4; ++nt)
            #pragma unroll
            for (int j = 0; j < 4; ++j) acc[mt][nt][j] = 0.f;

    // ---- band staging: each warp of the pair loads 16 rows of its band ----
    // rows b*32 + (wn)*16 .. +15 ; 256 float4 per warp -> 8 per lane
    const int row_base = b * 32 + wn * 16;
    auto stage_band = [&](const float* __restrict__ p, int e0) {
        #pragma unroll
        for (int i = 0; i < 8; ++i) {
            int f4i = lid + i * 32;                // 0..255
            int m   = row_base + (f4i >> 4);
            int c4  = f4i & 15;
            int e   = e0 + m;
            float4 v = (e < E) ? ((const float4*)p)[(size_t)e * 16 + c4]
                               : make_float4(0.f, 0.f, 0.f, 0.f);
            uint32_t off = sw128((uint32_t)(m * 128 + c4 * 8));
            split_store(smem + OFF_XHI + off, smem + OFF_XLO + off, v);
        }
    };

    // one 16-wide k-step on this warp's band/cols
    auto kstep = [&](int kk, uint32_t bhib, uint32_t blob, int kg) {
        uint32_t bhi[2][4], blo[2][4];
        ldsm4t(bhi[0], frag_addr(bhib, kg, wn * 32,      lid));
        ldsm4t(bhi[1], frag_addr(bhib, kg, wn * 32 + 16, lid));
        ldsm4t(blo[0], frag_addr(blob, kg, wn * 32,      lid));
        ldsm4t(blo[1], frag_addr(blob, kg, wn * 32 + 16, lid));
        #pragma unroll
        for (int mt = 0; mt < 2; ++mt) {
            uint32_t ahi[4], alo[4];
            ldsm4(ahi, frag_addr(sb + OFF_XHI, b * 32 + mt * 16, kk, lid));
            ldsm4(alo, frag_addr(sb + OFF_XLO, b * 32 + mt * 16, kk, lid));
            #pragma unroll
            for (int nt = 0; nt < 4; ++nt) {
                const uint32_t* bh = &bhi[nt >> 1][(nt & 1) * 2];
                const uint32_t* bl = &blo[nt >> 1][(nt & 1) * 2];
                mma16816(acc[mt][nt], ahi, bh);
                mma16816(acc[mt][nt], ahi, bl);
                mma16816(acc[mt][nt], alo, bh);
            }
        }
    };

    // ================= persistent tile loop (pair pipelines drift freely) ==========
    for (int t = blockIdx.x; t < ntiles; t += gridDim.x) {
        const int e0 = t * M_TILE;

        stage_band(src, e0);
        prefetch_l2((const char*)(dst + (size_t)(e0 + row_base) * 64) + (size_t)(lid & 15) * 64);
        pbar(bar_id);
        #pragma unroll
        for (int ks = 0; ks < 4; ++ks)
            kstep(ks * 16, sb + OFF_W1HI, sb + OFF_W1LO, ks * 16);
        pbar(bar_id);

        stage_band(dst, e0);
        prefetch_l2((const char*)(ea + (size_t)(e0 + row_base) * 64) + (size_t)(lid & 15) * 64);
        pbar(bar_id);
        #pragma unroll
        for (int ks = 0; ks < 4; ++ks)
            kstep(ks * 16, sb + OFF_W1HI, sb + OFF_W1LO, 64 + ks * 16);
        pbar(bar_id);

        stage_band(ea, e0);
        pbar(bar_id);
        #pragma unroll
        for (int ks = 0; ks < 4; ++ks)
            kstep(ks * 16, sb + OFF_W1HI, sb + OFF_W1LO, 128 + ks * 16);
        pbar(bar_id);                              // GEMM1 reads done; band free for H

        // ---- bias1 + ReLU + split -> H (reuse X hi/lo, band-local) ----
        {
            const float* b1s = (const float*)(smem + OFF_B1);
            #pragma unroll
            for (int mt = 0; mt < 2; ++mt)
                #pragma unroll
                for (int nt = 0; nt < 4; ++nt) {
                    int row = b * 32 + mt * 16 + (lid >> 2);
                    int col = wn * 32 + nt * 8 + (lid & 3) * 2;
                    float bc0 = b1s[col], bc1 = b1s[col + 1];
                    float h0 = fmaxf(acc[mt][nt][0] + bc0, 0.f);
                    float h1 = fmaxf(acc[mt][nt][1] + bc1, 0.f);
                    float h2 = fmaxf(acc[mt][nt][2] + bc0, 0.f);
                    float h3 = fmaxf(acc[mt][nt][3] + bc1, 0.f);
                    uint32_t hA = pack2bf(h0, h1);
                    uint32_t hB = pack2bf(h2, h3);
                    uint32_t lA = pack2bf(h0 - __uint_as_float(hA << 16),
                                          h1 - __uint_as_float(hA & 0xFFFF0000u));
                    uint32_t lB = pack2bf(h2 - __uint_as_float(hB << 16),
                                          h3 - __uint_as_float(hB & 0xFFFF0000u));
                    uint32_t oA = sw128((uint32_t)(row * 128 + col * 2));
                    uint32_t oB = sw128((uint32_t)((row + 8) * 128 + col * 2));
                    *(uint32_t*)(smem + OFF_XHI + oA) = hA;
                    *(uint32_t*)(smem + OFF_XLO + oA) = lA;
                    *(uint32_t*)(smem + OFF_XHI + oB) = hB;
                    *(uint32_t*)(smem + OFF_XLO + oB) = lB;
                    acc[mt][nt][0] = acc[mt][nt][1] = acc[mt][nt][2] = acc[mt][nt][3] = 0.f;
                }
        }
        pbar(bar_id);

        // ================= GEMM2 (K = 64) =================
        #pragma unroll
        for (int ks = 0; ks < 4; ++ks)
            kstep(ks * 16, sb + OFF_W2HI, sb + OFF_W2LO, ks * 16);
        pbar(bar_id);                              // H reads done; band free for next tile

        // ---- epilogue: + bias2, float2 stores; reset acc ----
        {
            const float* b2s = (const float*)(smem + OFF_B2);
            #pragma unroll
            for (int mt = 0; mt < 2; ++mt)
                #pragma unroll
                for (int nt = 0; nt < 4; ++nt) {
                    int row = b * 32 + mt * 16 + (lid >> 2);
                    int col = wn * 32 + nt * 8 + (lid & 3) * 2;
                    float bc0 = b2s[col], bc1 = b2s[col + 1];
                    int eA = e0 + row, eB = e0 + row + 8;
                    if (eA < E)
                        *(float2*)&out[(size_t)eA * 64 + col] =
                            make_float2(acc[mt][nt][0] + bc0, acc[mt][nt][1] + bc1);
                    if (eB < E)
                        *(float2*)&out[(size_t)eB * 64 + col] =
                            make_float2(acc[mt][nt][2] + bc0, acc[mt][nt][3] + bc1);
                    acc[mt][nt][0] = acc[mt][nt][1] = acc[mt][nt][2] = acc[mt][nt][3] = 0.f;
                }
        }
    }
}

extern "C" void kernel_launch(void* const* d_in, const int* in_sizes, int n_in,
                              void* d_out, int out_size)
{
    const float* src = (const float*)d_in[0];
    const float* dst = (const float*)d_in[1];
    const float* ea  = (const float*)d_in[2];
    const float* W1  = (const float*)d_in[5];
    const float* b1  = (const float*)d_in[6];
    const float* W2  = (const float*)d_in[7];
    const float* b2  = (const float*)d_in[8];
    float* out = (float*)d_out;

    int E = in_sizes[0] / 64;
    int ntiles = (E + M_TILE - 1) / M_TILE;

    cudaFuncSetAttribute(edge_mlp_mma,
                         cudaFuncAttributeMaxDynamicSharedMemorySize, SMEM_BYTES);

    int grid = 2 * 148;
    if (grid > ntiles) grid = ntiles;
    edge_mlp_mma<<<grid, THREADS, SMEM_BYTES>>>(src, dst, ea, W1, b1, W2, b2, out, E, ntiles);
}

// round 8
// speedup vs baseline: 1.0986x; 1.0986x over previous
#include <cuda_runtime.h>
#include <cstdint>

#define THREADS 256
#define M_TILE  128

// ---------------- SMEM layout (bytes), MMA buffers 1024-aligned ----------------
#define OFF_B1   0
#define OFF_B2   256
#define OFF_XHI  1024
#define OFF_XLO  (OFF_XHI + 16384)     // 17408
#define OFF_W1HI (OFF_XLO + 16384)     // 33792
#define OFF_W1LO (OFF_W1HI + 24576)    // 58368
#define OFF_W2HI (OFF_W1LO + 24576)    // 82944
#define OFF_W2LO (OFF_W2HI + 8192)     // 91136
#define SMEM_BYTES (OFF_W2LO + 8192)   // 99328  -> 2 CTAs/SM

// ---------------- helpers ----------------
__device__ __forceinline__ uint32_t smem_u32(const void* p) {
    uint32_t a;
    asm("{ .reg .u64 t; cvta.to.shared.u64 t, %1; cvt.u32.u64 %0, t; }" : "=r"(a) : "l"(p));
    return a;
}
__device__ __forceinline__ uint32_t sw128(uint32_t o) { return o ^ ((o >> 3) & 0x70); }

__device__ __forceinline__ uint32_t pack2bf(float e0, float e1) {
    uint32_t r;
    asm("cvt.rn.bf16x2.f32 %0, %1, %2;" : "=r"(r) : "f"(e1), "f"(e0));
    return r;
}

// split 4 fp32 into bf16 hi/lo, 8B store each
__device__ __forceinline__ void split_store(char* hip, char* lop, float4 v) {
    uint32_t h01 = pack2bf(v.x, v.y);
    uint32_t h23 = pack2bf(v.z, v.w);
    float f0 = __uint_as_float(h01 << 16);
    float f1 = __uint_as_float(h01 & 0xFFFF0000u);
    float f2 = __uint_as_float(h23 << 16);
    float f3 = __uint_as_float(h23 & 0xFFFF0000u);
    uint32_t l01 = pack2bf(v.x - f0, v.y - f1);
    uint32_t l23 = pack2bf(v.z - f2, v.w - f3);
    *reinterpret_cast<uint2*>(hip) = make_uint2(h01, h23);
    *reinterpret_cast<uint2*>(lop) = make_uint2(l01, l23);
}

__device__ __forceinline__ void ldsm4(uint32_t r[4], uint32_t addr) {
    asm volatile("ldmatrix.sync.aligned.m8n8.x4.shared.b16 {%0,%1,%2,%3}, [%4];"
        : "=r"(r[0]), "=r"(r[1]), "=r"(r[2]), "=r"(r[3]) : "r"(addr));
}
__device__ __forceinline__ void ldsm4t(uint32_t r[4], uint32_t addr) {
    asm volatile("ldmatrix.sync.aligned.m8n8.x4.trans.shared.b16 {%0,%1,%2,%3}, [%4];"
        : "=r"(r[0]), "=r"(r[1]), "=r"(r[2]), "=r"(r[3]) : "r"(addr));
}
__device__ __forceinline__ void mma16816(float c[4], const uint32_t a[4], const uint32_t b[2]) {
    asm volatile(
        "mma.sync.aligned.m16n8k16.row.col.f32.bf16.bf16.f32 "
        "{%0,%1,%2,%3}, {%4,%5,%6,%7}, {%8,%9}, {%0,%1,%2,%3};"
        : "+f"(c[0]), "+f"(c[1]), "+f"(c[2]), "+f"(c[3])
        : "r"(a[0]), "r"(a[1]), "r"(a[2]), "r"(a[3]), "r"(b[0]), "r"(b[1]));
}
__device__ __forceinline__ uint32_t frag_addr(uint32_t base, int rbase, int cbase, int lane) {
    int row  = rbase + (lane & 15);
    int colb = cbase * 2 + (lane & 16);
    return base + sw128((uint32_t)(row * 128 + colb));
}
__device__ __forceinline__ void prefetch_l2(const void* p) {
    asm volatile("prefetch.global.L2 [%0];" :: "l"(p));
}

__global__ __launch_bounds__(THREADS, 2)
void edge_mlp_mma(const float* __restrict__ src, const float* __restrict__ dst,
                  const float* __restrict__ ea,
                  const float* __restrict__ W1, const float* __restrict__ b1,
                  const float* __restrict__ W2, const float* __restrict__ b2,
                  float* __restrict__ out, int E, int ntiles)
{
    extern __shared__ char smem[];
    const uint32_t sb = smem_u32(smem);
    const int tid = threadIdx.x;
    const int lid = tid & 31;
    const int wid = tid >> 5;

    const int wm = wid & 3;   // M group: rows 32*wm .. +31
    const int wn = wid >> 2;  // N group: cols 32*wn .. +31

    // ================= ONE-TIME: biases + weights =================
    if (tid < 64) {
        ((float*)(smem + OFF_B1))[tid] = b1[tid];
        ((float*)(smem + OFF_B2))[tid] = b2[tid];
    }
    #pragma unroll
    for (int i = 0; i < 12; ++i) {
        int idx = tid + i * THREADS;               // float4 index, 0..3071
        uint32_t off = sw128((uint32_t)((idx >> 4) * 128 + (idx & 15) * 8));
        float4 v = ((const float4*)W1)[idx];
        split_store(smem + OFF_W1HI + off, smem + OFF_W1LO + off, v);
    }
    #pragma unroll
    for (int i = 0; i < 4; ++i) {
        int idx = tid + i * THREADS;               // 0..1023
        uint32_t off = sw128((uint32_t)((idx >> 4) * 128 + (idx & 15) * 8));
        float4 v = ((const float4*)W2)[idx];
        split_store(smem + OFF_W2HI + off, smem + OFF_W2LO + off, v);
    }

    float acc[2][4][4];
    #pragma unroll
    for (int mt = 0; mt < 2; ++mt)
        #pragma unroll
        for (int nt = 0; nt < 4; ++nt)
            #pragma unroll
            for (int j = 0; j < 4; ++j) acc[mt][nt][j] = 0.f;

    // ---- X staging: batched LDG pass (MLP=8), then split/STS pass ----
    auto stage_x = [&](const float* __restrict__ p, int e0, const float* __restrict__ pre) {
        float4 v[8];
        #pragma unroll
        for (int i = 0; i < 8; ++i) {
            int idx = tid + i * THREADS;           // 0..2047
            int e = e0 + (idx >> 4);
            v[i] = (e < E) ? ((const float4*)p)[(size_t)e * 16 + (idx & 15)]
                           : make_float4(0.f, 0.f, 0.f, 0.f);
        }
        if (pre) prefetch_l2((const char*)pre + (size_t)tid * 128);   // next 32KB segment
        #pragma unroll
        for (int i = 0; i < 8; ++i) {
            int idx = tid + i * THREADS;
            uint32_t off = sw128((uint32_t)((idx >> 4) * 128 + (idx & 15) * 8));
            split_store(smem + OFF_XHI + off, smem + OFF_XLO + off, v[i]);
        }
    };

    // one 16-wide k-step: A from X hi/lo at col kk, B from weight buffers at row kg
    auto kstep = [&](int kk, uint32_t bhib, uint32_t blob, int kg) {
        uint32_t bhi[2][4], blo[2][4];
        ldsm4t(bhi[0], frag_addr(bhib, kg, wn * 32,      lid));
        ldsm4t(bhi[1], frag_addr(bhib, kg, wn * 32 + 16, lid));
        ldsm4t(blo[0], frag_addr(blob, kg, wn * 32,      lid));
        ldsm4t(blo[1], frag_addr(blob, kg, wn * 32 + 16, lid));
        #pragma unroll
        for (int mt = 0; mt < 2; ++mt) {
            uint32_t ahi[4], alo[4];
            ldsm4(ahi, frag_addr(sb + OFF_XHI, wm * 32 + mt * 16, kk, lid));
            ldsm4(alo, frag_addr(sb + OFF_XLO, wm * 32 + mt * 16, kk, lid));
            #pragma unroll
            for (int nt = 0; nt < 4; ++nt) {
                const uint32_t* bh = &bhi[nt >> 1][(nt & 1) * 2];
                const uint32_t* bl = &blo[nt >> 1][(nt & 1) * 2];
                mma16816(acc[mt][nt], ahi, bh);
                mma16816(acc[mt][nt], ahi, bl);
                mma16816(acc[mt][nt], alo, bh);
            }
        }
    };

    // ================= persistent tile loop =================
    for (int t = blockIdx.x; t < ntiles; t += gridDim.x) {
        const int e0 = t * M_TILE;
        const float* row0 = src + (size_t)e0 * 64;

        stage_x(src, e0, dst + (size_t)e0 * 64);
        __syncthreads();
        #pragma unroll
        for (int ks = 0; ks < 4; ++ks)
            kstep(ks * 16, sb + OFF_W1HI, sb + OFF_W1LO, ks * 16);
        __syncthreads();

        stage_x(dst, e0, ea + (size_t)e0 * 64);
        __syncthreads();
        #pragma unroll
        for (int ks = 0; ks < 4; ++ks)
            kstep(ks * 16, sb + OFF_W1HI, sb + OFF_W1LO, 64 + ks * 16);
        __syncthreads();

        {
            int tn = t + gridDim.x;
            const float* nxt = (tn < ntiles) ? src + (size_t)tn * M_TILE * 64 : row0;
            stage_x(ea, e0, nxt);
        }
        __syncthreads();
        #pragma unroll
        for (int ks = 0; ks < 4; ++ks)
            kstep(ks * 16, sb + OFF_W1HI, sb + OFF_W1LO, 128 + ks * 16);
        __syncthreads();                           // GEMM1 reads done; X free for H

        // ---- bias1 + ReLU + split -> H (reuse X hi/lo) ----
        {
            const float* b1s = (const float*)(smem + OFF_B1);
            #pragma unroll
            for (int mt = 0; mt < 2; ++mt)
                #pragma unroll
                for (int nt = 0; nt < 4; ++nt) {
                    int row = wm * 32 + mt * 16 + (lid >> 2);
                    int col = wn * 32 + nt * 8 + (lid & 3) * 2;
                    float bc0 = b1s[col], bc1 = b1s[col + 1];
                    float h0 = fmaxf(acc[mt][nt][0] + bc0, 0.f);
                    float h1 = fmaxf(acc[mt][nt][1] + bc1, 0.f);
                    float h2 = fmaxf(acc[mt][nt][2] + bc0, 0.f);
                    float h3 = fmaxf(acc[mt][nt][3] + bc1, 0.f);
                    uint32_t hA = pack2bf(h0, h1);
                    uint32_t hB = pack2bf(h2, h3);
                    uint32_t lA = pack2bf(h0 - __uint_as_float(hA << 16),
                                          h1 - __uint_as_float(hA & 0xFFFF0000u));
                    uint32_t lB = pack2bf(h2 - __uint_as_float(hB << 16),
                                          h3 - __uint_as_float(hB & 0xFFFF0000u));
                    uint32_t oA = sw128((uint32_t)(row * 128 + col * 2));
                    uint32_t oB = sw128((uint32_t)((row + 8) * 128 + col * 2));
                    *(uint32_t*)(smem + OFF_XHI + oA) = hA;
                    *(uint32_t*)(smem + OFF_XLO + oA) = lA;
                    *(uint32_t*)(smem + OFF_XHI + oB) = hB;
                    *(uint32_t*)(smem + OFF_XLO + oB) = lB;
                    acc[mt][nt][0] = acc[mt][nt][1] = acc[mt][nt][2] = acc[mt][nt][3] = 0.f;
                }
        }
        __syncthreads();

        // ================= GEMM2 (K = 64) =================
        #pragma unroll
        for (int ks = 0; ks < 4; ++ks)
            kstep(ks * 16, sb + OFF_W2HI, sb + OFF_W2LO, ks * 16);

        // ---- epilogue: + bias2, float2 stores; reset acc for next tile ----
        {
            const float* b2s = (const float*)(smem + OFF_B2);
            #pragma unroll
            for (int mt = 0; mt < 2; ++mt)
                #pragma unroll
                for (int nt = 0; nt < 4; ++nt) {
                    int row = wm * 32 + mt * 16 + (lid >> 2);
                    int col = wn * 32 + nt * 8 + (lid & 3) * 2;
                    float bc0 = b2s[col], bc1 = b2s[col + 1];
                    int eA = e0 + row, eB = e0 + row + 8;
                    if (eA < E)
                        *(float2*)&out[(size_t)eA * 64 + col] =
                            make_float2(acc[mt][nt][0] + bc0, acc[mt][nt][1] + bc1);
                    if (eB < E)
                        *(float2*)&out[(size_t)eB * 64 + col] =
                            make_float2(acc[mt][nt][2] + bc0, acc[mt][nt][3] + bc1);
                    acc[mt][nt][0] = acc[mt][nt][1] = acc[mt][nt][2] = acc[mt][nt][3] = 0.f;
                }
        }
        __syncthreads();                           // H reads done before next stage_x
    }
}

extern "C" void kernel_launch(void* const* d_in, const int* in_sizes, int n_in,
                              void* d_out, int out_size)
{
    const float* src = (const float*)d_in[0];
    const float* dst = (const float*)d_in[1];
    const float* ea  = (const float*)d_in[2];
    const float* W1  = (const float*)d_in[5];
    const float* b1  = (const float*)d_in[6];
    const float* W2  = (const float*)d_in[7];
    const float* b2  = (const float*)d_in[8];
    float* out = (float*)d_out;

    int E = in_sizes[0] / 64;
    int ntiles = (E + M_TILE - 1) / M_TILE;

    cudaFuncSetAttribute(edge_mlp_mma,
                         cudaFuncAttributeMaxDynamicSharedMemorySize, SMEM_BYTES);

    int grid = 2 * 148;
    if (grid > ntiles) grid = ntiles;
    edge_mlp_mma<<<grid, THREADS, SMEM_BYTES>>>(src, dst, ea, W1, b1, W2, b2, out, E, ntiles);
}